// round 7
// baseline (speedup 1.0000x reference)
#include <cuda_runtime.h>
#include <math_constants.h>

#define NN 262144
#define EE 2097152
#define EPS 1e-5f

// ---------------- scratch (static __device__, no allocations) ----------------
__device__ int   g_deg[NN];
__device__ int   g_offs[NN];
__device__ int   g_cursor[NN];
__device__ int   g_bsums[256];
__device__ int   g_src[EE];
__device__ float g_a1[NN * 16];
__device__ float g_h1[NN * 16];
__device__ float g_a2[NN * 32];

// ---------------- kernels ----------------

__global__ void k_init(unsigned* out) {
    int i = blockIdx.x * blockDim.x + threadIdx.x;
    if (i < NN) { g_deg[i] = 0; g_cursor[i] = 0; }
    if (i < 64 * 32) out[i] = 0u;   // pooled output accumulates float-bits via atomicMax
}

__global__ void k_hist(const int* __restrict__ ei) {
    int e = blockIdx.x * blockDim.x + threadIdx.x;
    if (e >= EE) return;
    int d = ei[EE + e];             // edge_index row 1 (dst), int32
    atomicAdd(&g_deg[d], 1);
}

// block-local exclusive scan of deg (1024 per block), block totals to g_bsums
__global__ void k_scan1(void) {
    __shared__ int s[1024];
    int t = threadIdx.x;
    int i = blockIdx.x * 1024 + t;
    int v = g_deg[i];
    s[t] = v;
    __syncthreads();
    for (int off = 1; off < 1024; off <<= 1) {
        int add = (t >= off) ? s[t - off] : 0;
        __syncthreads();
        s[t] += add;
        __syncthreads();
    }
    g_offs[i] = s[t] - v;                  // exclusive
    if (t == 1023) g_bsums[blockIdx.x] = s[t];
}

// exclusive scan of 256 block sums (one block)
__global__ void k_scan2(void) {
    __shared__ int s[256];
    int t = threadIdx.x;
    int v = g_bsums[t];
    s[t] = v;
    __syncthreads();
    for (int off = 1; off < 256; off <<= 1) {
        int add = (t >= off) ? s[t - off] : 0;
        __syncthreads();
        s[t] += add;
        __syncthreads();
    }
    g_bsums[t] = s[t] - v;                 // exclusive
}

__global__ void k_scan3(void) {
    int i = blockIdx.x * blockDim.x + threadIdx.x;
    if (i < NN) g_offs[i] += g_bsums[i >> 10];
}

__global__ void k_scatter(const int* __restrict__ ei) {
    int e = blockIdx.x * blockDim.x + threadIdx.x;
    if (e >= EE) return;
    int s = ei[e];                  // row 0 (src)
    int d = ei[EE + e];             // row 1 (dst)
    int p = atomicAdd(&g_cursor[d], 1);
    g_src[g_offs[d] + p] = s;
}

// a1[n,ch] = x[n]*W1[0,ch] + pos[n]·W1[1:4,ch] + b1[ch]
__global__ void k_a1(const float* __restrict__ x, const float* __restrict__ pos,
                     const float* __restrict__ W1, const float* __restrict__ b1) {
    int idx = blockIdx.x * blockDim.x + threadIdx.x;
    if (idx >= NN * 16) return;
    int ch = idx & 15;
    int n  = idx >> 4;
    float xv = x[n];
    float px = pos[3 * n], py = pos[3 * n + 1], pz = pos[3 * n + 2];
    g_a1[idx] = fmaf(xv, W1[ch],
                fmaf(px, W1[16 + ch],
                fmaf(py, W1[32 + ch],
                fmaf(pz, W1[48 + ch], b1[ch]))));
}

// gather-max layer1: 2 dsts per warp, lane%16 = channel; fused -c1, BN, ReLU
__global__ void k_gather1(const float* __restrict__ pos,
                          const float* __restrict__ W1,
                          const float* __restrict__ m1, const float* __restrict__ v1,
                          const float* __restrict__ w1, const float* __restrict__ bb1) {
    int lane = threadIdx.x & 31;
    int warp = (blockIdx.x * blockDim.x + threadIdx.x) >> 5;
    int ch = lane & 15;
    int d = warp * 2 + (lane >> 4);
    if (d >= NN) return;
    int start = g_offs[d];
    int deg   = g_deg[d];
    float m = -CUDART_INF_F;
    for (int i = 0; i < deg; i++) {
        int s = g_src[start + i];
        m = fmaxf(m, g_a1[s * 16 + ch]);
    }
    float agg;
    if (deg == 0) {
        agg = 0.f;
    } else {
        float px = pos[3 * d], py = pos[3 * d + 1], pz = pos[3 * d + 2];
        agg = m - fmaf(px, W1[16 + ch], fmaf(py, W1[32 + ch], pz * W1[48 + ch]));
    }
    float sc = w1[ch] * rsqrtf(v1[ch] + EPS);
    float y = fmaf(agg - m1[ch], sc, bb1[ch]);
    g_h1[d * 16 + ch] = y > 0.f ? y : 0.f;
}

// a2[n,ch] = sum_k h1[n,k]*W2[k,ch] + pos[n]·W2[16:19,ch] + b2[ch]
__global__ void k_a2(const float* __restrict__ pos,
                     const float* __restrict__ W2, const float* __restrict__ b2) {
    int idx = blockIdx.x * blockDim.x + threadIdx.x;
    if (idx >= NN * 32) return;
    int ch = idx & 31;
    int n  = idx >> 5;
    float acc = b2[ch];
    const float* h = &g_h1[n * 16];
#pragma unroll
    for (int k = 0; k < 16; k++) acc = fmaf(h[k], W2[k * 32 + ch], acc);
    float px = pos[3 * n], py = pos[3 * n + 1], pz = pos[3 * n + 2];
    acc = fmaf(px, W2[16 * 32 + ch], acc);
    acc = fmaf(py, W2[17 * 32 + ch], acc);
    acc = fmaf(pz, W2[18 * 32 + ch], acc);
    g_a2[idx] = acc;
}

// gather-max layer2 + BN + ReLU + fused voxel max-pool.
// 1 warp per dst (lane = channel), each warp iterates 128 dsts;
// block (8 warps) privatizes the 64x32 pool in smem, flushes once.
__global__ void k_gather2_pool(const float* __restrict__ pos,
                               const float* __restrict__ W2,
                               const float* __restrict__ m2, const float* __restrict__ v2,
                               const float* __restrict__ w2, const float* __restrict__ bb2,
                               unsigned* __restrict__ out) {
    __shared__ unsigned spool[64 * 32];
    for (int i = threadIdx.x; i < 64 * 32; i += blockDim.x) spool[i] = 0u;
    __syncthreads();

    int lane   = threadIdx.x & 31;
    int warpid = threadIdx.x >> 5;
    int wg     = blockIdx.x * 8 + warpid;
    int ch     = lane;

    // per-channel constants (loop-invariant)
    float sc    = w2[ch] * rsqrtf(v2[ch] + EPS);
    float mean  = m2[ch];
    float beta  = bb2[ch];
    float cwx = W2[16 * 32 + ch], cwy = W2[17 * 32 + ch], cwz = W2[18 * 32 + ch];

    for (int j = 0; j < 128; j++) {
        int d = wg * 128 + j;
        int start = g_offs[d];
        int deg   = g_deg[d];
        float m = -CUDART_INF_F;
        for (int i = 0; i < deg; i++) {
            int s = g_src[start + i];
            m = fmaxf(m, g_a2[s * 32 + ch]);
        }
        float px = pos[3 * d], py = pos[3 * d + 1], pz = pos[3 * d + 2];
        float agg = (deg == 0) ? 0.f
                               : m - fmaf(px, cwx, fmaf(py, cwy, pz * cwz));
        float y = fmaf(agg - mean, sc, beta);
        float h = y > 0.f ? y : 0.f;   // strictly +0 for non-positive (never -0)

        int gx = (int)floorf(px * (1.f / 16.f));
        int gy = (int)floorf(py * (1.f / 16.f));
        int cl = gx + gy * 8;
        cl = min(max(cl, 0), 63);
        // h >= +0  =>  raw float bits are monotone under unsigned max
        atomicMax(&spool[cl * 32 + ch], __float_as_uint(h));
    }
    __syncthreads();
    for (int i = threadIdx.x; i < 64 * 32; i += blockDim.x) {
        unsigned v = spool[i];
        if (v) atomicMax(&out[i], v);
    }
}

// ---------------- launch ----------------
extern "C" void kernel_launch(void* const* d_in, const int* in_sizes, int n_in,
                              void* d_out, int out_size) {
    const float* x    = (const float*)d_in[0];
    const float* pos  = (const float*)d_in[1];
    const int*   ei   = (const int*)d_in[2];   // edge_index as int32, shape (2, E) row-major
    const float* W1   = (const float*)d_in[3];
    const float* b1   = (const float*)d_in[4];
    const float* m1   = (const float*)d_in[5];
    const float* v1   = (const float*)d_in[6];
    const float* w1   = (const float*)d_in[7];
    const float* bb1  = (const float*)d_in[8];
    const float* W2   = (const float*)d_in[9];
    const float* b2   = (const float*)d_in[10];
    const float* m2   = (const float*)d_in[11];
    const float* v2   = (const float*)d_in[12];
    const float* w2   = (const float*)d_in[13];
    const float* bb2  = (const float*)d_in[14];
    unsigned* out = (unsigned*)d_out;

    k_init<<<(NN + 255) / 256, 256>>>(out);
    k_hist<<<(EE + 255) / 256, 256>>>(ei);
    k_scan1<<<NN / 1024, 1024>>>();
    k_scan2<<<1, 256>>>();
    k_scan3<<<(NN + 255) / 256, 256>>>();
    k_scatter<<<(EE + 255) / 256, 256>>>(ei);
    k_a1<<<(NN * 16 + 255) / 256, 256>>>(x, pos, W1, b1);
    k_gather1<<<(NN / 2 * 32 + 255) / 256, 256>>>(pos, W1, m1, v1, w1, bb1);
    k_a2<<<(NN * 32 + 255) / 256, 256>>>(pos, W2, b2);
    k_gather2_pool<<<NN / (8 * 128), 256>>>(pos, W2, m2, v2, w2, bb2, out);
}

// round 10
// speedup vs baseline: 1.5682x; 1.5682x over previous
#include <cuda_runtime.h>
#include <math_constants.h>

#define NN 262144
#define EE 2097152
#define EPS 1e-5f

// ---------------- scratch (static __device__, no allocations) ----------------
__device__ int   g_deg[NN];
__device__ int   g_offs[NN];
__device__ int   g_bsums[256];
__device__ int   g_src[EE];
__device__ float g_a1[NN * 16];
__device__ float g_a2[NN * 32];

// ---------------- kernels ----------------

__global__ void k_init(unsigned* out) {
    int i = blockIdx.x * blockDim.x + threadIdx.x;
    if (i < NN) g_deg[i] = 0;
    if (i < 64 * 32) out[i] = 0u;   // pooled output accumulates float-bits via atomicMax
}

__global__ void k_hist(const int* __restrict__ ei) {
    int e = blockIdx.x * blockDim.x + threadIdx.x;
    if (e >= EE) return;
    int d = __ldg(&ei[EE + e]);     // edge_index row 1 (dst), int32
    atomicAdd(&g_deg[d], 1);
}

// block-local exclusive scan of deg (1024 per block), block totals to g_bsums
__global__ void k_scan1(void) {
    __shared__ int s[1024];
    int t = threadIdx.x;
    int i = blockIdx.x * 1024 + t;
    int v = g_deg[i];
    s[t] = v;
    __syncthreads();
    for (int off = 1; off < 1024; off <<= 1) {
        int add = (t >= off) ? s[t - off] : 0;
        __syncthreads();
        s[t] += add;
        __syncthreads();
    }
    g_offs[i] = s[t] - v;                  // exclusive
    if (t == 1023) g_bsums[blockIdx.x] = s[t];
}

// exclusive scan of 256 block sums (one block)
__global__ void k_scan2(void) {
    __shared__ int s[256];
    int t = threadIdx.x;
    int v = g_bsums[t];
    s[t] = v;
    __syncthreads();
    for (int off = 1; off < 256; off <<= 1) {
        int add = (t >= off) ? s[t - off] : 0;
        __syncthreads();
        s[t] += add;
        __syncthreads();
    }
    g_bsums[t] = s[t] - v;                 // exclusive
}

__global__ void k_scan3(void) {
    int i = blockIdx.x * blockDim.x + threadIdx.x;
    if (i < NN) g_offs[i] += g_bsums[i >> 10];
}

// scatter src ids; atomicAdd directly on g_offs (post: g_offs[d] = seg end)
__global__ void k_scatter(const int* __restrict__ ei) {
    int e = blockIdx.x * blockDim.x + threadIdx.x;
    if (e >= EE) return;
    int s = __ldg(&ei[e]);          // row 0 (src)
    int d = __ldg(&ei[EE + e]);     // row 1 (dst)
    int p = atomicAdd(&g_offs[d], 1);
    g_src[p] = s;
}

// a1[n,ch] = x[n]*W1[0,ch] + pos[n]·W1[1:4,ch] + b1[ch]
__global__ void k_a1(const float* __restrict__ x, const float* __restrict__ pos,
                     const float* __restrict__ W1, const float* __restrict__ b1) {
    int idx = blockIdx.x * blockDim.x + threadIdx.x;
    if (idx >= NN * 16) return;
    int ch = idx & 15;
    int n  = idx >> 4;
    float xv = __ldg(&x[n]);
    float px = __ldg(&pos[3 * n]), py = __ldg(&pos[3 * n + 1]), pz = __ldg(&pos[3 * n + 2]);
    g_a1[idx] = fmaf(xv, W1[ch],
                fmaf(px, W1[16 + ch],
                fmaf(py, W1[32 + ch],
                fmaf(pz, W1[48 + ch], b1[ch]))));
}

// gather-max layer1 (2 dsts/warp, lane%16 = channel) fused with BN+ReLU and
// the 16->32 linear of layer 2 (via warp shuffles): writes a2 directly.
__global__ void __launch_bounds__(256)
k_gather1_a2(const float* __restrict__ pos,
             const float* __restrict__ W1,
             const float* __restrict__ m1, const float* __restrict__ v1,
             const float* __restrict__ w1, const float* __restrict__ bb1,
             const float* __restrict__ W2, const float* __restrict__ b2) {
    __shared__ float sW2[19 * 32];
    __shared__ float sB2[32];
    for (int i = threadIdx.x; i < 19 * 32; i += blockDim.x) sW2[i] = W2[i];
    if (threadIdx.x < 32) sB2[threadIdx.x] = b2[threadIdx.x];
    __syncthreads();

    int lane = threadIdx.x & 31;
    int warp = (blockIdx.x * blockDim.x + threadIdx.x) >> 5;
    int ch = lane & 15;                    // layer-1 channel / sub-lane
    int d = warp * 2 + (lane >> 4);
    int end = g_offs[d];                   // post-scatter: segment end
    int deg = g_deg[d];
    int start = end - deg;

    float m = -CUDART_INF_F;
    int i = 0;
    for (; i + 4 <= deg; i += 4) {
        int s0 = __ldg(&g_src[start + i]);
        int s1 = __ldg(&g_src[start + i + 1]);
        int s2 = __ldg(&g_src[start + i + 2]);
        int s3 = __ldg(&g_src[start + i + 3]);
        float v0 = __ldg(&g_a1[s0 * 16 + ch]);
        float v1 = __ldg(&g_a1[s1 * 16 + ch]);
        float v2 = __ldg(&g_a1[s2 * 16 + ch]);
        float v3 = __ldg(&g_a1[s3 * 16 + ch]);
        m = fmaxf(m, fmaxf(fmaxf(v0, v1), fmaxf(v2, v3)));
    }
    for (; i < deg; i++) {
        int s = __ldg(&g_src[start + i]);
        m = fmaxf(m, __ldg(&g_a1[s * 16 + ch]));
    }

    float px = __ldg(&pos[3 * d]), py = __ldg(&pos[3 * d + 1]), pz = __ldg(&pos[3 * d + 2]);
    float agg = (deg == 0) ? 0.f
              : m - fmaf(px, W1[16 + ch], fmaf(py, W1[32 + ch], pz * W1[48 + ch]));
    float sc = w1[ch] * rsqrtf(v1[ch] + EPS);
    float y = fmaf(agg - m1[ch], sc, bb1[ch]);
    float h = y > 0.f ? y : 0.f;           // h1[d][ch], register-resident

    // layer-2 linear: a2[d][c] = b2[c] + sum_k h1[d][k]*W2[k][c] + pos·W2[16:19][c]
    int c0 = 2 * ch, c1 = 2 * ch + 1;
    float acc0 = sB2[c0], acc1 = sB2[c1];
    int base = lane & 16;
#pragma unroll
    for (int k = 0; k < 16; k++) {
        float hk = __shfl_sync(0xFFFFFFFFu, h, base | k);
        acc0 = fmaf(hk, sW2[k * 32 + c0], acc0);
        acc1 = fmaf(hk, sW2[k * 32 + c1], acc1);
    }
    acc0 = fmaf(px, sW2[16 * 32 + c0], fmaf(py, sW2[17 * 32 + c0], fmaf(pz, sW2[18 * 32 + c0], acc0)));
    acc1 = fmaf(px, sW2[16 * 32 + c1], fmaf(py, sW2[17 * 32 + c1], fmaf(pz, sW2[18 * 32 + c1], acc1)));
    reinterpret_cast<float2*>(g_a2)[d * 16 + ch] = make_float2(acc0, acc1);
}

// gather-max layer2 + BN + ReLU + fused voxel max-pool.
// 1 warp per dst (lane = channel); 512 blocks x 8 warps, 64 dsts per warp.
__global__ void __launch_bounds__(256)
k_gather2_pool(const float* __restrict__ pos,
               const float* __restrict__ W2,
               const float* __restrict__ m2, const float* __restrict__ v2,
               const float* __restrict__ w2, const float* __restrict__ bb2,
               unsigned* __restrict__ out) {
    __shared__ unsigned spool[64 * 32];
    for (int i = threadIdx.x; i < 64 * 32; i += blockDim.x) spool[i] = 0u;
    __syncthreads();

    int lane   = threadIdx.x & 31;
    int warpid = threadIdx.x >> 5;
    int wg     = blockIdx.x * 8 + warpid;
    int ch     = lane;

    float sc   = w2[ch] * rsqrtf(v2[ch] + EPS);
    float mean = m2[ch];
    float beta = bb2[ch];
    float cwx = W2[16 * 32 + ch], cwy = W2[17 * 32 + ch], cwz = W2[18 * 32 + ch];

    for (int j = 0; j < 64; j++) {
        int d = wg * 64 + j;
        int end = g_offs[d];
        int deg = g_deg[d];
        int start = end - deg;
        float m = -CUDART_INF_F;
        int i = 0;
        for (; i + 4 <= deg; i += 4) {
            int s0 = __ldg(&g_src[start + i]);
            int s1 = __ldg(&g_src[start + i + 1]);
            int s2 = __ldg(&g_src[start + i + 2]);
            int s3 = __ldg(&g_src[start + i + 3]);
            float v0 = __ldg(&g_a2[s0 * 32 + ch]);
            float v1 = __ldg(&g_a2[s1 * 32 + ch]);
            float v2r = __ldg(&g_a2[s2 * 32 + ch]);
            float v3 = __ldg(&g_a2[s3 * 32 + ch]);
            m = fmaxf(m, fmaxf(fmaxf(v0, v1), fmaxf(v2r, v3)));
        }
        for (; i < deg; i++) {
            int s = __ldg(&g_src[start + i]);
            m = fmaxf(m, __ldg(&g_a2[s * 32 + ch]));
        }
        float px = __ldg(&pos[3 * d]), py = __ldg(&pos[3 * d + 1]), pz = __ldg(&pos[3 * d + 2]);
        float agg = (deg == 0) ? 0.f
                  : m - fmaf(px, cwx, fmaf(py, cwy, pz * cwz));
        float y = fmaf(agg - mean, sc, beta);
        float h = y > 0.f ? y : 0.f;   // strictly +0 for non-positive (never -0)

        int gx = (int)floorf(px * (1.f / 16.f));
        int gy = (int)floorf(py * (1.f / 16.f));
        int cl = gx + gy * 8;
        cl = min(max(cl, 0), 63);
        // h >= +0  =>  raw float bits are monotone under unsigned max
        atomicMax(&spool[cl * 32 + ch], __float_as_uint(h));
    }
    __syncthreads();
    for (int i = threadIdx.x; i < 64 * 32; i += blockDim.x) {
        unsigned v = spool[i];
        if (v) atomicMax(&out[i], v);
    }
}

// ---------------- launch ----------------
extern "C" void kernel_launch(void* const* d_in, const int* in_sizes, int n_in,
                              void* d_out, int out_size) {
    const float* x    = (const float*)d_in[0];
    const float* pos  = (const float*)d_in[1];
    const int*   ei   = (const int*)d_in[2];   // edge_index as int32, shape (2, E) row-major
    const float* W1   = (const float*)d_in[3];
    const float* b1   = (const float*)d_in[4];
    const float* m1   = (const float*)d_in[5];
    const float* v1   = (const float*)d_in[6];
    const float* w1   = (const float*)d_in[7];
    const float* bb1  = (const float*)d_in[8];
    const float* W2   = (const float*)d_in[9];
    const float* b2   = (const float*)d_in[10];
    const float* m2   = (const float*)d_in[11];
    const float* v2   = (const float*)d_in[12];
    const float* w2   = (const float*)d_in[13];
    const float* bb2  = (const float*)d_in[14];
    unsigned* out = (unsigned*)d_out;

    k_init<<<(NN + 255) / 256, 256>>>(out);
    k_hist<<<(EE + 255) / 256, 256>>>(ei);
    k_scan1<<<NN / 1024, 1024>>>();
    k_scan2<<<1, 256>>>();
    k_scan3<<<(NN + 255) / 256, 256>>>();
    k_scatter<<<(EE + 255) / 256, 256>>>(ei);
    k_a1<<<(NN * 16 + 255) / 256, 256>>>(x, pos, W1, b1);
    k_gather1_a2<<<NN / 2 * 32 / 256, 256>>>(pos, W1, m1, v1, w1, bb1, W2, b2);
    k_gather2_pool<<<512, 256>>>(pos, W2, m2, v2, w2, bb2, out);
}